// round 3
// baseline (speedup 1.0000x reference)
#include <cuda_runtime.h>
#include <cstdint>

// CIN (xDeepFM) fused kernel: one CTA per batch row, 512 threads.
// 3 CIN layers as SMEM-resident GEMMs; B tile stored pre-duplicated so
// packed f32x2 FMAs need zero MOVs; W staged by cp.async double buffer.

#define BATCH 2048
#define FIELD 39
#define DIM   64
#define KT    32
#define NTHR  512

#define L0 256
#define L1 128
#define L2 64
#define LTOT (L0 + L1 + L2)

#define WSTRIDE  (KT * L0)        // 8192 floats / W buffer
#define BDSTRIDE (KT * DIM * 2)   // 4096 floats / dup'd B buffer

typedef unsigned long long ull;

__device__ __forceinline__ ull dup2(float v) {
    ull r; asm("mov.b64 %0, {%1, %1};" : "=l"(r) : "f"(v)); return r;
}
__device__ __forceinline__ void fma2(ull& d, ull a, ull b) {
    asm("fma.rn.f32x2 %0, %1, %2, %3;" : "=l"(d) : "l"(a), "l"(b), "l"(d));
}
__device__ __forceinline__ float2 unpack2(ull v) {
    float2 f; asm("mov.b64 {%0, %1}, %2;" : "=f"(f.x), "=f"(f.y) : "l"(v));
    return f;
}
__device__ __forceinline__ void cpasync16(uint32_t s, const void* g) {
    asm volatile("cp.async.cg.shared.global [%0], [%1], 16;" :: "r"(s), "l"(g));
}
__device__ __forceinline__ void cpasync_commit() {
    asm volatile("cp.async.commit_group;");
}
__device__ __forceinline__ void cpasync_wait0() {
    asm volatile("cp.async.wait_group 0;");
}

// SMEM layout (floats)
#define OFF_X0 0
#define OFF_H0 (OFF_X0 + FIELD * DIM)        // 2496
#define OFF_H1 (OFF_H0 + L0 * DIM)
#define OFF_H2 (OFF_H1 + L1 * DIM)
#define OFF_WS (OFF_H2 + L2 * DIM)           // 2 * WSTRIDE
#define OFF_BD (OFF_WS + 2 * WSTRIDE)        // 2 * BDSTRIDE
#define SMEM_FLOATS (OFF_BD + 2 * BDSTRIDE)  // 55744 -> 222,976 B
#define SMEM_BYTES (SMEM_FLOATS * 4)

// One CIN layer: C[L,64] = W^T[L,K] * P[K,64], P[(i,j),d]=x0[i,d]*hprev[j,d]
// TL l's and TD d's per thread; acc packed over l-pairs; B pre-duplicated.
template<int L, int TL, int TD, int FK>
__device__ __forceinline__ void cin_layer(
    const float* __restrict__ Wg, const float* __restrict__ bias,
    const float* __restrict__ x0s, const float* __restrict__ hprev,
    float* __restrict__ hout, float* __restrict__ Ws, float* __restrict__ Bd)
{
    constexpr int K  = FIELD * FK;
    constexpr int T  = (K + KT - 1) / KT;
    constexpr int DG = DIM / TD;
    constexpr int NP = TL / 2;
    static_assert((L / TL) * DG == NTHR, "tile/thread mismatch");

    const int tid = threadIdx.x;
    const int dg  = tid % DG;
    const int lg  = tid / DG;
    const int l0  = lg * TL;
    const int d0  = dg * TD;

    ull acc[NP][TD];
    #pragma unroll
    for (int p = 0; p < NP; p++)
        #pragma unroll
        for (int q = 0; q < TD; q++) acc[p][q] = 0ull;

    const uint32_t ws_u32 = (uint32_t)__cvta_generic_to_shared(Ws);

    // ---- stage W tile t via cp.async ----
    auto stage_w = [&](int t) {
        const int k0 = t * KT;
        const int n16 = min(KT, K - k0) * L / 4;   // 16B chunks
        const uint32_t dst = ws_u32 + (uint32_t)((t & 1) * WSTRIDE * 4);
        const float4* src = (const float4*)(Wg + (size_t)k0 * L);
        for (int idx = tid; idx < n16; idx += NTHR)
            cpasync16(dst + idx * 16, src + idx);
        cpasync_commit();
    };
    // ---- build duplicated B tile t ----
    auto build_b = [&](int t) {
        const int k0 = t * KT;
        const int n  = min(KT, K - k0) * DIM;
        float* B = Bd + (t & 1) * BDSTRIDE;
        for (int e = tid; e < n; e += NTHR) {
            const int kk = e >> 6, d = e & 63;
            const int gk = k0 + kk;
            const int i = gk / FK, j = gk - i * FK;
            const float v = x0s[i * DIM + d] * hprev[j * DIM + d];
            *(ull*)(B + kk * (2 * DIM) + 2 * d) = dup2(v);
        }
    };

    stage_w(0);
    build_b(0);
    cpasync_wait0();
    __syncthreads();

    for (int t = 0; t < T; t++) {
        const int cur = t & 1;
        const int kcnt = min(KT, K - t * KT);
        const bool more = (t + 1 < T);

        if (more) stage_w(t + 1);   // prefetch next W (async)

        const float* Wsb = Ws + cur * WSTRIDE;
        const float* Bb  = Bd + cur * BDSTRIDE;
        #pragma unroll 4
        for (int kk = 0; kk < kcnt; kk++) {
            const ull* wp = (const ull*)(Wsb + kk * L + l0);
            const ulonglong2* bp =
                (const ulonglong2*)(Bb + kk * (2 * DIM) + 2 * d0);
            ull b[TD];
            #pragma unroll
            for (int j = 0; j < TD / 2; j++) {
                const ulonglong2 v = bp[j];
                b[2 * j] = v.x; b[2 * j + 1] = v.y;
            }
            ull w[NP];
            #pragma unroll
            for (int p = 0; p < NP; p++) w[p] = wp[p];
            #pragma unroll
            for (int p = 0; p < NP; p++)
                #pragma unroll
                for (int q = 0; q < TD; q++) fma2(acc[p][q], w[p], b[q]);
        }

        if (more) build_b(t + 1);   // build next B while cp.async lands
        cpasync_wait0();
        __syncthreads();
    }

    // ---- epilogue: add bias, store hout [l][d] ----
    #pragma unroll
    for (int p = 0; p < NP; p++) {
        const int la = l0 + 2 * p;
        const float ba = bias[la];
        const float bb = bias[la + 1];
        #pragma unroll
        for (int q = 0; q < TD; q++) {
            const float2 v = unpack2(acc[p][q]);
            hout[la * DIM + d0 + q]       = v.x + ba;
            hout[(la + 1) * DIM + d0 + q] = v.y + bb;
        }
    }
}

__global__ void __launch_bounds__(NTHR, 1) cin_kernel(
    const void* __restrict__ feat_ids_raw,
    const float* __restrict__ emb,
    const float* __restrict__ W0, const float* __restrict__ b0,
    const float* __restrict__ W1, const float* __restrict__ b1,
    const float* __restrict__ W2, const float* __restrict__ b2,
    float* __restrict__ out)
{
    extern __shared__ float sm[];
    float* x0s = sm + OFF_X0;
    float* h0  = sm + OFF_H0;
    float* h1  = sm + OFF_H1;
    float* h2  = sm + OFF_H2;
    float* Ws  = sm + OFF_WS;
    float* Bd  = sm + OFF_BD;

    __shared__ long long sids[FIELD];
    __shared__ int is64flag;

    const int b   = blockIdx.x;
    const int tid = threadIdx.x;

    // Detect id element width (int64 vs int32): int64 ids < 13105 => every
    // high 32-bit word is zero.
    if (tid == 0) {
        const unsigned int* w = (const unsigned int*)feat_ids_raw;
        int f = 1;
        #pragma unroll
        for (int t = 0; t < 32; t++)
            if (w[2 * t + 1] != 0u) { f = 0; break; }
        is64flag = f;
    }
    __syncthreads();

    if (tid < FIELD) {
        long long id;
        if (is64flag)
            id = ((const long long*)feat_ids_raw)[(size_t)b * FIELD + tid];
        else
            id = ((const int*)feat_ids_raw)[(size_t)b * FIELD + tid];
        sids[tid] = id;
    }
    __syncthreads();

    // Gather x0 = emb[feat_ids[b]]  -> SMEM [39][64]
    for (int t = tid; t < FIELD * DIM; t += NTHR) {
        const int r = t >> 6;
        const int d = t & 63;
        x0s[t] = emb[(size_t)sids[r] * DIM + d];
    }
    __syncthreads();

    cin_layer<L0, 8, 4, FIELD>(W0, b0, x0s, x0s, h0, Ws, Bd);
    __syncthreads();
    cin_layer<L1, 4, 4, L0>(W1, b1, x0s, h0, h1, Ws, Bd);
    __syncthreads();
    cin_layer<L2, 4, 2, L1>(W2, b2, x0s, h1, h2, Ws, Bd);
    __syncthreads();

    // Final reduce over embedding dim, write [b, 448]
    float* outb = out + (size_t)b * LTOT;
    for (int l = tid; l < LTOT; l += NTHR) {
        const float* src = (l < L0) ? (h0 + l * DIM)
                         : (l < L0 + L1) ? (h1 + (l - L0) * DIM)
                         : (h2 + (l - L0 - L1) * DIM);
        const float4* s4 = (const float4*)src;
        float s = 0.f;
        #pragma unroll
        for (int d = 0; d < DIM / 4; d++) {
            const float4 v = s4[d];
            s += (v.x + v.y) + (v.z + v.w);
        }
        outb[l] = s;
    }
}

extern "C" void kernel_launch(void* const* d_in, const int* in_sizes, int n_in,
                              void* d_out, int out_size) {
    const void*  feat = d_in[0];
    const float* emb  = (const float*)d_in[1];
    const float* W0   = (const float*)d_in[2];
    const float* b0   = (const float*)d_in[3];
    const float* W1   = (const float*)d_in[4];
    const float* b1   = (const float*)d_in[5];
    const float* W2   = (const float*)d_in[6];
    const float* b2   = (const float*)d_in[7];
    float* out = (float*)d_out;

    cudaFuncSetAttribute(cin_kernel,
                         cudaFuncAttributeMaxDynamicSharedMemorySize,
                         SMEM_BYTES);
    cin_kernel<<<BATCH, NTHR, SMEM_BYTES>>>(feat, emb, W0, b0, W1, b1,
                                            W2, b2, out);
}

// round 5
// speedup vs baseline: 2.3698x; 2.3698x over previous
#include <cuda_runtime.h>
#include <cstdint>

// CIN (xDeepFM) fused kernel: one CTA per batch row, 512 threads.
// 3 CIN layers as SMEM-resident GEMMs with on-the-fly outer-product B tiles.
// k-sliced register blocking: every layer runs a uniform 8x4 per-thread tile
// (16 packed f32x2 FMAs per processed k), with S=512/(2L) k-slices reduced
// once per layer via packed adds.

#define BATCH 2048
#define FIELD 39
#define DIM   64
#define KT    32
#define NTHR  512

#define L0 256
#define L1 128
#define L2 64
#define LTOT (L0 + L1 + L2)

#define WSTRIDE (KT * L0)     // 8192 floats per W buffer
#define BSTRIDE (KT * DIM)    // 2048 floats per B buffer

typedef unsigned long long ull;

__device__ __forceinline__ ull dup2(float v) {
    ull r; asm("mov.b64 %0, {%1, %1};" : "=l"(r) : "f"(v)); return r;
}
__device__ __forceinline__ void fma2(ull& d, ull a, ull b) {
    asm("fma.rn.f32x2 %0, %1, %2, %3;" : "=l"(d) : "l"(a), "l"(b), "l"(d));
}
__device__ __forceinline__ ull add2(ull a, ull b) {
    ull d; asm("add.rn.f32x2 %0, %1, %2;" : "=l"(d) : "l"(a), "l"(b));
    return d;
}
__device__ __forceinline__ float2 unpack2(ull v) {
    float2 f; asm("mov.b64 {%0, %1}, %2;" : "=f"(f.x), "=f"(f.y) : "l"(v));
    return f;
}

// SMEM layout (floats)
#define OFF_X0 0
#define OFF_H0 (OFF_X0 + FIELD * DIM)          // 2496
#define OFF_H1 (OFF_H0 + L0 * DIM)
#define OFF_H2 (OFF_H1 + L1 * DIM)
#define OFF_WS (OFF_H2 + L2 * DIM)             // 2*WSTRIDE
#define OFF_BS (OFF_WS + 2 * WSTRIDE)          // 2*BSTRIDE
#define SMEM_FLOATS (OFF_BS + 2 * BSTRIDE)     // 51648 -> 206,592 B
#define SMEM_BYTES (SMEM_FLOATS * 4)

// One CIN layer: C[L,64] = W^T[L,K] * P[K,64], P[(i,j),d]=x0[i,d]*hprev[j,d]
// Uniform per-thread tile: TL=8 l's (4 packed pairs) x TD=4 d's.
// S = 512/(2L) k-slices; partials reduced via SMEM scratch (aliases Ws).
template<int L, int FK>
__device__ __forceinline__ void cin_layer(
    const float* __restrict__ Wg, const float* __restrict__ bias,
    const float* __restrict__ x0s, const float* __restrict__ hprev,
    float* __restrict__ hout, float* __restrict__ Ws, float* __restrict__ Bs,
    float* __restrict__ scratch)
{
    constexpr int TL = 8, TD = 4, NP = 4;
    constexpr int S  = NTHR / (2 * L);          // 1 / 2 / 4
    constexpr int K  = FIELD * FK;
    constexpr int T  = (K + KT - 1) / KT;
    constexpr int NW4 = (KT * L) / (4 * NTHR);  // 4 / 2 / 1

    const int tid   = threadIdx.x;
    const int slice = tid / (2 * L);            // 0..S-1
    const int sid   = tid % (2 * L);
    const int lg    = sid >> 4;
    const int dg    = sid & 15;
    const int l0    = lg * TL;
    const int d0    = dg * TD;

    ull acc[NP][TD];
    #pragma unroll
    for (int p = 0; p < NP; p++)
        #pragma unroll
        for (int q = 0; q < TD; q++) acc[p][q] = 0ull;

    float4 wreg[NW4];

    // ---- per-k body ----
    auto body = [&](const float* Wsb, const float* Bsb, int kk) {
        const float4 bf = *(const float4*)(Bsb + kk * DIM + d0);
        ull bv[TD];
        bv[0] = dup2(bf.x); bv[1] = dup2(bf.y);
        bv[2] = dup2(bf.z); bv[3] = dup2(bf.w);
        const ulonglong2* wp = (const ulonglong2*)(Wsb + kk * L + l0);
        const ulonglong2 wa = wp[0];
        const ulonglong2 wb = wp[1];
        ull w[NP] = {wa.x, wa.y, wb.x, wb.y};
        #pragma unroll
        for (int p = 0; p < NP; p++)
            #pragma unroll
            for (int q = 0; q < TD; q++) fma2(acc[p][q], w[p], bv[q]);
    };

    // ---- prologue: stage tile 0 directly ----
    {
        const int kcnt = min(KT, K);
        const int n4 = kcnt * L / 4;
        const float4* src = (const float4*)Wg;
        float4* dst = (float4*)Ws;
        for (int idx = tid; idx < n4; idx += NTHR) dst[idx] = src[idx];
        const int n = kcnt * DIM;
        for (int e = tid; e < n; e += NTHR) {
            const int kk = e >> 6, d = e & 63;
            const int i = kk / FK, j = kk - i * FK;
            Bs[e] = x0s[i * DIM + d] * hprev[j * DIM + d];
        }
    }
    __syncthreads();

    for (int t = 0; t < T; t++) {
        const int cur  = t & 1;
        const int nxt  = cur ^ 1;
        const int kcnt = min(KT, K - t * KT);
        const bool more = (t + 1 < T);
        const int nk0  = (t + 1) * KT;
        const int nn4  = more ? (min(KT, K - nk0) * L / 4) : 0;

        // issue next W tile's LDGs early (latency hides behind compute)
        if (more) {
            const float4* src = (const float4*)(Wg + (size_t)nk0 * L);
            #pragma unroll
            for (int u = 0; u < NW4; u++) {
                const int idx = tid + u * NTHR;
                if (idx < nn4) wreg[u] = src[idx];
            }
        }

        // ---- compute current tile (k-sliced) ----
        {
            const float* Wsb = Ws + cur * WSTRIDE;
            const float* Bsb = Bs + cur * BSTRIDE;
            if (kcnt == KT) {
                #pragma unroll 8
                for (int kk = slice; kk < KT; kk += S) body(Wsb, Bsb, kk);
            } else {
                for (int kk = slice; kk < kcnt; kk += S) body(Wsb, Bsb, kk);
            }
        }

        // ---- commit next tile ----
        if (more) {
            float4* dst = (float4*)(Ws + nxt * WSTRIDE);
            #pragma unroll
            for (int u = 0; u < NW4; u++) {
                const int idx = tid + u * NTHR;
                if (idx < nn4) dst[idx] = wreg[u];
            }
            float* Bsb = Bs + nxt * BSTRIDE;
            const int n = min(KT, K - nk0) * DIM;
            for (int e = tid; e < n; e += NTHR) {
                const int kk = e >> 6, d = e & 63;
                const int gk = nk0 + kk;
                const int i = gk / FK, j = gk - i * FK;
                Bsb[e] = x0s[i * DIM + d] * hprev[j * DIM + d];
            }
        }
        __syncthreads();
    }

    // ---- k-slice reduction (scratch aliases Ws; all reads of Ws done) ----
    if (S > 1) {
        if (slice != 0) {
            ull* dst = (ull*)(scratch +
                ((size_t)(slice - 1) * 2 * L + sid) * (NP * TD * 2));
            #pragma unroll
            for (int p = 0; p < NP; p++)
                #pragma unroll
                for (int q = 0; q < TD; q++) dst[p * TD + q] = acc[p][q];
        }
        __syncthreads();
        if (slice == 0) {
            #pragma unroll
            for (int s = 1; s < S; s++) {
                const ull* src = (const ull*)(scratch +
                    ((size_t)(s - 1) * 2 * L + sid) * (NP * TD * 2));
                #pragma unroll
                for (int p = 0; p < NP; p++)
                    #pragma unroll
                    for (int q = 0; q < TD; q++)
                        acc[p][q] = add2(acc[p][q], src[p * TD + q]);
            }
        }
    }

    // ---- epilogue: add bias, store hout [l][d] (slice 0 only) ----
    if (slice == 0) {
        #pragma unroll
        for (int p = 0; p < NP; p++) {
            const int la = l0 + 2 * p;
            const float ba = bias[la];
            const float bb = bias[la + 1];
            #pragma unroll
            for (int q = 0; q < TD; q++) {
                const float2 v = unpack2(acc[p][q]);
                hout[la * DIM + d0 + q]       = v.x + ba;
                hout[(la + 1) * DIM + d0 + q] = v.y + bb;
            }
        }
    }
}

__global__ void __launch_bounds__(NTHR, 1) cin_kernel(
    const void* __restrict__ feat_ids_raw,
    const float* __restrict__ emb,
    const float* __restrict__ W0, const float* __restrict__ b0,
    const float* __restrict__ W1, const float* __restrict__ b1,
    const float* __restrict__ W2, const float* __restrict__ b2,
    float* __restrict__ out)
{
    extern __shared__ float sm[];
    float* x0s = sm + OFF_X0;
    float* h0  = sm + OFF_H0;
    float* h1  = sm + OFF_H1;
    float* h2  = sm + OFF_H2;
    float* Ws  = sm + OFF_WS;
    float* Bs  = sm + OFF_BS;
    float* scratch = sm + OFF_WS;   // reused after GEMM loop

    __shared__ long long sids[FIELD];
    __shared__ int is64flag;

    const int b   = blockIdx.x;
    const int tid = threadIdx.x;

    // Detect id element width (int64 vs int32): int64 ids < 13105 => every
    // high 32-bit word is zero.
    if (tid == 0) {
        const unsigned int* w = (const unsigned int*)feat_ids_raw;
        int f = 1;
        #pragma unroll
        for (int t = 0; t < 32; t++)
            if (w[2 * t + 1] != 0u) { f = 0; break; }
        is64flag = f;
    }
    __syncthreads();

    if (tid < FIELD) {
        long long id;
        if (is64flag)
            id = ((const long long*)feat_ids_raw)[(size_t)b * FIELD + tid];
        else
            id = ((const int*)feat_ids_raw)[(size_t)b * FIELD + tid];
        sids[tid] = id;
    }
    __syncthreads();

    // Gather x0 = emb[feat_ids[b]]  -> SMEM [39][64]
    for (int t = tid; t < FIELD * DIM; t += NTHR) {
        const int r = t >> 6;
        const int d = t & 63;
        x0s[t] = emb[(size_t)sids[r] * DIM + d];
    }
    __syncthreads();

    cin_layer<L0, FIELD>(W0, b0, x0s, x0s, h0, Ws, Bs, scratch);
    __syncthreads();
    cin_layer<L1, L0>(W1, b1, x0s, h0, h1, Ws, Bs, scratch);
    __syncthreads();
    cin_layer<L2, L1>(W2, b2, x0s, h1, h2, Ws, Bs, scratch);
    __syncthreads();

    // Final reduce over embedding dim, write [b, 448]
    float* outb = out + (size_t)b * LTOT;
    for (int l = tid; l < LTOT; l += NTHR) {
        const float* src = (l < L0) ? (h0 + l * DIM)
                         : (l < L0 + L1) ? (h1 + (l - L0) * DIM)
                         : (h2 + (l - L0 - L1) * DIM);
        const float4* s4 = (const float4*)src;
        float s = 0.f;
        #pragma unroll
        for (int d = 0; d < DIM / 4; d++) {
            const float4 v = s4[d];
            s += (v.x + v.y) + (v.z + v.w);
        }
        outb[l] = s;
    }
}

extern "C" void kernel_launch(void* const* d_in, const int* in_sizes, int n_in,
                              void* d_out, int out_size) {
    const void*  feat = d_in[0];
    const float* emb  = (const float*)d_in[1];
    const float* W0   = (const float*)d_in[2];
    const float* b0   = (const float*)d_in[3];
    const float* W1   = (const float*)d_in[4];
    const float* b1   = (const float*)d_in[5];
    const float* W2   = (const float*)d_in[6];
    const float* b2   = (const float*)d_in[7];
    float* out = (float*)d_out;

    cudaFuncSetAttribute(cin_kernel,
                         cudaFuncAttributeMaxDynamicSharedMemorySize,
                         SMEM_BYTES);
    cin_kernel<<<BATCH, NTHR, SMEM_BYTES>>>(feat, emb, W0, b0, W1, b1,
                                            W2, b2, out);
}